// round 6
// baseline (speedup 1.0000x reference)
#include <cuda_runtime.h>
#include <cstdint>

#define H   2048
#define I1  1024        // inter
#define I2  2048        // 2*inter
#define E   32
#define MAXT 8192
#define MAXPAIR (2*MAXT)
#define TM 64
#define TN 64
#define TK 16
#define MAXTILES 320    // >= 2*T/TM + E = 288

// ---------------- device scratch (static: no allocations allowed) ----------------
__device__ float g_h[MAXPAIR * I1];          // 64 MB swiglu outputs per (token,expert) pair
__device__ float g_logits[MAXT * E];
__device__ int   g_counts[E];
__device__ int   g_cursor[E];
__device__ int   g_offsets[E];
__device__ int   g_tok_e[MAXT * 2];
__device__ float g_tok_g[MAXT * 2];
__device__ int   g_pair_tok[MAXPAIR];
__device__ float g_pair_gate[MAXPAIR];
__device__ int   g_tile_expert[MAXTILES];
__device__ int   g_tile_rowbase[MAXTILES];
__device__ int   g_tile_pairbase[MAXTILES];
__device__ int   g_n_tiles;

// ---------------- packed f32x2 helpers (Blackwell FFMA2 path) ----------------
#define FMA2(d,a,b) asm("fma.rn.f32x2 %0, %1, %2, %0;" : "+l"(d) : "l"(a), "l"(b))

__device__ __forceinline__ unsigned long long packdup(float f) {
    unsigned long long r;
    asm("mov.b64 %0, {%1, %1};" : "=l"(r) : "f"(f));
    return r;
}
__device__ __forceinline__ void unpack2(unsigned long long d, float& lo, float& hi) {
    asm("mov.b64 {%0, %1}, %2;" : "=f"(lo), "=f"(hi) : "l"(d));
}

// ---------------- init: zero small control arrays ----------------
__global__ void init_kernel() {
    int i = threadIdx.x;
    if (i < E) { g_counts[i] = 0; g_cursor[i] = 0; }
    if (i == 0) g_n_tiles = 0;
}

// ---------------- router GEMM: logits[T,32] = x @ gate_w^T + gate_b ----------------
__global__ __launch_bounds__(256) void router_gemm(const float* __restrict__ x,
                                                   const float* __restrict__ gw,
                                                   const float* __restrict__ gb) {
    __shared__ __align__(16) float xs[32][36];
    __shared__ __align__(16) float ws[32][36];
    int tid = threadIdx.x;
    int tx = tid & 7;          // expert group: 4 experts each
    int ty = tid >> 3;         // token 0..31
    int tbase = blockIdx.x * 32;
    int lrow = tid >> 3;       // 0..31 (load row)
    int lk4  = (tid & 7) * 4;  // 0..28

    float acc[4] = {0.f, 0.f, 0.f, 0.f};
    const float* xp = x  + (size_t)(tbase + lrow) * H + lk4;
    const float* wp = gw + (size_t)lrow * H + lk4;

    for (int kb = 0; kb < H; kb += 32) {
        float4 xv = *(const float4*)(xp + kb);
        float4 wv = *(const float4*)(wp + kb);
        *(float4*)&xs[lrow][lk4] = xv;
        ws[lk4 + 0][lrow] = wv.x;
        ws[lk4 + 1][lrow] = wv.y;
        ws[lk4 + 2][lrow] = wv.z;
        ws[lk4 + 3][lrow] = wv.w;
        __syncthreads();
#pragma unroll
        for (int k = 0; k < 32; ++k) {
            float xv1 = xs[ty][k];
            float4 w4 = *(const float4*)&ws[k][tx * 4];
            acc[0] = fmaf(xv1, w4.x, acc[0]);
            acc[1] = fmaf(xv1, w4.y, acc[1]);
            acc[2] = fmaf(xv1, w4.z, acc[2]);
            acc[3] = fmaf(xv1, w4.w, acc[3]);
        }
        __syncthreads();
    }
    int t = tbase + ty;
#pragma unroll
    for (int j = 0; j < 4; ++j)
        g_logits[t * E + tx * 4 + j] = acc[j] + gb[tx * 4 + j];
}

// ---------------- softmax + top-2 per token; count tokens per expert ----------------
__global__ void topk_kernel(int T) {
    int warp = (blockIdx.x * blockDim.x + threadIdx.x) >> 5;
    int lane = threadIdx.x & 31;
    if (warp >= T) return;
    float l = g_logits[warp * E + lane];

    float m = l;
#pragma unroll
    for (int o = 16; o; o >>= 1) m = fmaxf(m, __shfl_xor_sync(0xffffffffu, m, o));
    float p = __expf(l - m);
    float s = p;
#pragma unroll
    for (int o = 16; o; o >>= 1) s += __shfl_xor_sync(0xffffffffu, s, o);
    float prob = p / s;

    // top-1 (tie -> lower index, matching lax.top_k)
    float v = prob; int idx = lane;
#pragma unroll
    for (int o = 16; o; o >>= 1) {
        float vo = __shfl_xor_sync(0xffffffffu, v, o);
        int   io = __shfl_xor_sync(0xffffffffu, idx, o);
        if (vo > v || (vo == v && io < idx)) { v = vo; idx = io; }
    }
    int e0 = idx; float g0 = v;

    float v2 = (lane == e0) ? -1.0f : prob; int idx2 = lane;
#pragma unroll
    for (int o = 16; o; o >>= 1) {
        float vo = __shfl_xor_sync(0xffffffffu, v2, o);
        int   io = __shfl_xor_sync(0xffffffffu, idx2, o);
        if (vo > v2 || (vo == v2 && io < idx2)) { v2 = vo; idx2 = io; }
    }
    int e1 = idx2; float g1 = v2;

    if (lane == 0) {
        g_tok_e[warp * 2 + 0] = e0; g_tok_g[warp * 2 + 0] = g0;
        g_tok_e[warp * 2 + 1] = e1; g_tok_g[warp * 2 + 1] = g1;
        atomicAdd(&g_counts[e0], 1);
        atomicAdd(&g_counts[e1], 1);
    }
}

// ---------------- scan: expert offsets + tile list ----------------
__global__ void scan_kernel() {
    if (threadIdx.x != 0) return;
    int off = 0, nt = 0;
    for (int e = 0; e < E; ++e) {
        g_offsets[e] = off;
        int c = g_counts[e];
        for (int rb = 0; rb < c; rb += TM) {
            g_tile_expert[nt]   = e;
            g_tile_rowbase[nt]  = rb;
            g_tile_pairbase[nt] = off + rb;
            nt++;
        }
        off += c;
    }
    g_n_tiles = nt;
}

// ---------------- scatter tokens into per-expert contiguous pair lists ----------------
__global__ void scatter_kernel(int T) {
    int t = blockIdx.x * blockDim.x + threadIdx.x;
    if (t >= T) return;
#pragma unroll
    for (int j = 0; j < 2; ++j) {
        int e = g_tok_e[t * 2 + j];
        int pos = g_offsets[e] + atomicAdd(&g_cursor[e], 1);
        g_pair_tok[pos]  = t;
        g_pair_gate[pos] = g_tok_g[t * 2 + j];
    }
}

// ---------------- fc1: gathered GEMM [rows,2I] = X[tok] @ W1_e^T, fused swiglu -> g_h ----------------
__global__ __launch_bounds__(256) void fc1_kernel(const float* __restrict__ x,
                                                  const float* __restrict__ w1,
                                                  const float* __restrict__ b1) {
    int tile = blockIdx.x;
    if (tile >= g_n_tiles) return;
    int e         = g_tile_expert[tile];
    int rowbase   = g_tile_rowbase[tile];
    int pair_base = g_tile_pairbase[tile];
    int rows = g_counts[e] - rowbase; if (rows > TM) rows = TM;
    int nbase = blockIdx.y * TN;

    __shared__ __align__(16) float a_s[TK][TM + 4];
    __shared__ __align__(16) float b_s[TK][TN + 2];

    int tid = threadIdx.x;
    int tx = tid & 15, ty = tid >> 4;
    int lrow = tid >> 2, lk4 = (tid & 3) << 2;

    int arow = (lrow < rows) ? lrow : 0;
    int tok  = g_pair_tok[pair_base + arow];
    const float* aptr = x  + (size_t)tok * H + lk4;
    const float* bptr = w1 + ((size_t)e * I2 + (nbase + lrow)) * H + lk4;

    unsigned long long acc[4][2];
#pragma unroll
    for (int i = 0; i < 4; ++i) { acc[i][0] = 0ull; acc[i][1] = 0ull; }

    float4 areg = *(const float4*)aptr;
    float4 breg = *(const float4*)bptr;

    const int NK = H / TK;
    for (int kc = 0; kc < NK; ++kc) {
        a_s[lk4 + 0][lrow] = areg.x; a_s[lk4 + 1][lrow] = areg.y;
        a_s[lk4 + 2][lrow] = areg.z; a_s[lk4 + 3][lrow] = areg.w;
        b_s[lk4 + 0][lrow] = breg.x; b_s[lk4 + 1][lrow] = breg.y;
        b_s[lk4 + 2][lrow] = breg.z; b_s[lk4 + 3][lrow] = breg.w;
        __syncthreads();
        if (kc + 1 < NK) {
            areg = *(const float4*)(aptr + (kc + 1) * TK);
            breg = *(const float4*)(bptr + (kc + 1) * TK);
        }
#pragma unroll
        for (int k = 0; k < TK; ++k) {
            float4 av = *(const float4*)&a_s[k][ty * 4];
            const unsigned long long* brow = (const unsigned long long*)&b_s[k][0];
            unsigned long long bv0 = brow[tx * 2], bv1 = brow[tx * 2 + 1];
            unsigned long long a0 = packdup(av.x), a1 = packdup(av.y);
            unsigned long long a2 = packdup(av.z), a3 = packdup(av.w);
            FMA2(acc[0][0], a0, bv0); FMA2(acc[0][1], a0, bv1);
            FMA2(acc[1][0], a1, bv0); FMA2(acc[1][1], a1, bv1);
            FMA2(acc[2][0], a2, bv0); FMA2(acc[2][1], a2, bv1);
            FMA2(acc[3][0], a3, bv0); FMA2(acc[3][1], a3, bv1);
        }
        __syncthreads();
    }

    const float* b1e = b1 + e * I2;
#pragma unroll
    for (int i = 0; i < 4; ++i) {
        int lm = ty * 4 + i;
        if (lm >= rows) continue;
        int pair = pair_base + lm;
#pragma unroll
        for (int jj = 0; jj < 2; ++jj) {
            float zg, zl;
            unpack2(acc[i][jj], zg, zl);
            int ncol = nbase + tx * 4 + jj * 2;        // even column -> glu path
            zg += b1e[ncol];
            zl += b1e[ncol + 1];
            zg = fminf(zg, 7.0f);
            zl = fminf(fmaxf(zl, -7.0f), 7.0f);
            float hv = zg * (1.0f / (1.0f + __expf(-1.702f * zg))) * (zl + 1.0f);
            g_h[pair * I1 + (ncol >> 1)] = hv;
        }
    }
}

// ---------------- fc2: [rows,H] = h @ W2_e^T (+b2), scaled by gate, atomic-scatter to out ----------------
__global__ __launch_bounds__(256) void fc2_kernel(const float* __restrict__ w2,
                                                  const float* __restrict__ b2,
                                                  float* __restrict__ out,
                                                  int total_pairs) {
    int tile = blockIdx.x;
    if (tile >= g_n_tiles) return;
    int e         = g_tile_expert[tile];
    int rowbase   = g_tile_rowbase[tile];
    int pair_base = g_tile_pairbase[tile];
    int rows = g_counts[e] - rowbase; if (rows > TM) rows = TM;
    int nbase = blockIdx.y * TN;

    __shared__ __align__(16) float a_s[TK][TM + 4];
    __shared__ __align__(16) float b_s[TK][TN + 2];

    int tid = threadIdx.x;
    int tx = tid & 15, ty = tid >> 4;
    int lrow = tid >> 2, lk4 = (tid & 3) << 2;

    int prow = pair_base + lrow;
    if (prow >= total_pairs) prow = total_pairs - 1;
    const float* aptr = g_h + (size_t)prow * I1 + lk4;
    const float* bptr = w2  + ((size_t)e * H + (nbase + lrow)) * I1 + lk4;

    unsigned long long acc[4][2];
#pragma unroll
    for (int i = 0; i < 4; ++i) { acc[i][0] = 0ull; acc[i][1] = 0ull; }

    float4 areg = *(const float4*)aptr;
    float4 breg = *(const float4*)bptr;

    const int NK = I1 / TK;
    for (int kc = 0; kc < NK; ++kc) {
        a_s[lk4 + 0][lrow] = areg.x; a_s[lk4 + 1][lrow] = areg.y;
        a_s[lk4 + 2][lrow] = areg.z; a_s[lk4 + 3][lrow] = areg.w;
        b_s[lk4 + 0][lrow] = breg.x; b_s[lk4 + 1][lrow] = breg.y;
        b_s[lk4 + 2][lrow] = breg.z; b_s[lk4 + 3][lrow] = breg.w;
        __syncthreads();
        if (kc + 1 < NK) {
            areg = *(const float4*)(aptr + (kc + 1) * TK);
            breg = *(const float4*)(bptr + (kc + 1) * TK);
        }
#pragma unroll
        for (int k = 0; k < TK; ++k) {
            float4 av = *(const float4*)&a_s[k][ty * 4];
            const unsigned long long* brow = (const unsigned long long*)&b_s[k][0];
            unsigned long long bv0 = brow[tx * 2], bv1 = brow[tx * 2 + 1];
            unsigned long long a0 = packdup(av.x), a1 = packdup(av.y);
            unsigned long long a2 = packdup(av.z), a3 = packdup(av.w);
            FMA2(acc[0][0], a0, bv0); FMA2(acc[0][1], a0, bv1);
            FMA2(acc[1][0], a1, bv0); FMA2(acc[1][1], a1, bv1);
            FMA2(acc[2][0], a2, bv0); FMA2(acc[2][1], a2, bv1);
            FMA2(acc[3][0], a3, bv0); FMA2(acc[3][1], a3, bv1);
        }
        __syncthreads();
    }

    const float* b2e = b2 + e * H;
#pragma unroll
    for (int i = 0; i < 4; ++i) {
        int lm = ty * 4 + i;
        if (lm >= rows) continue;
        int pair = pair_base + lm;
        int tok  = g_pair_tok[pair];
        float gate = g_pair_gate[pair];
        float* orow = out + (size_t)tok * H;
#pragma unroll
        for (int jj = 0; jj < 2; ++jj) {
            float y0, y1;
            unpack2(acc[i][jj], y0, y1);
            int ncol = nbase + tx * 4 + jj * 2;
            atomicAdd(orow + ncol,     gate * (y0 + b2e[ncol]));
            atomicAdd(orow + ncol + 1, gate * (y1 + b2e[ncol + 1]));
        }
    }
}

// ---------------- launch ----------------
extern "C" void kernel_launch(void* const* d_in, const int* in_sizes, int n_in,
                              void* d_out, int out_size) {
    const float* x  = (const float*)d_in[0];
    const float* gw = (const float*)d_in[1];
    const float* gb = (const float*)d_in[2];
    const float* w1 = (const float*)d_in[3];
    const float* b1 = (const float*)d_in[4];
    const float* w2 = (const float*)d_in[5];
    const float* b2 = (const float*)d_in[6];
    float* out = (float*)d_out;
    int T = in_sizes[0] / H;   // 8192

    cudaMemsetAsync(d_out, 0, (size_t)out_size * sizeof(float));
    init_kernel<<<1, 64>>>();
    router_gemm<<<T / 32, 256>>>(x, gw, gb);
    topk_kernel<<<(T + 7) / 8, 256>>>(T);
    scan_kernel<<<1, 32>>>();
    scatter_kernel<<<(T + 255) / 256, 256>>>(T);

    dim3 g1(MAXTILES, I2 / TN);   // (320, 32)
    fc1_kernel<<<g1, 256>>>(x, w1, b1);
    dim3 g2(MAXTILES, H / TN);    // (320, 32)
    fc2_kernel<<<g2, 256>>>(w2, b2, out, 2 * T);
}

// round 7
// speedup vs baseline: 1.0016x; 1.0016x over previous
#include <cuda_runtime.h>
#include <cstdint>

#define H   2048
#define I1  1024        // inter
#define I2  2048        // 2*inter
#define E   32
#define MAXT 8192
#define MAXPAIR (2*MAXT)
#define TM 64
#define TN 64
#define TK 16
#define MAXTILES 320    // >= 2*T/TM + E = 288

// ---------------- device scratch (static: no allocations allowed) ----------------
__device__ float g_h[MAXPAIR * I1];          // 64 MB swiglu outputs per (token,expert) pair
__device__ float g_logits[MAXT * E];
__device__ int   g_counts[E];
__device__ int   g_cursor[E];
__device__ int   g_offsets[E];
__device__ int   g_tok_e[MAXT * 2];
__device__ float g_tok_g[MAXT * 2];
__device__ int   g_pair_tok[MAXPAIR];
__device__ float g_pair_gate[MAXPAIR];
__device__ int   g_tile_expert[MAXTILES];
__device__ int   g_tile_rowbase[MAXTILES];
__device__ int   g_tile_pairbase[MAXTILES];
__device__ int   g_n_tiles;

// ---------------- packed f32x2 helpers (Blackwell FFMA2 path) ----------------
#define FMA2(d,a,b) asm("fma.rn.f32x2 %0, %1, %2, %0;" : "+l"(d) : "l"(a), "l"(b))

__device__ __forceinline__ unsigned long long packdup(float f) {
    unsigned long long r;
    asm("mov.b64 %0, {%1, %1};" : "=l"(r) : "f"(f));
    return r;
}
__device__ __forceinline__ void unpack2(unsigned long long d, float& lo, float& hi) {
    asm("mov.b64 {%0, %1}, %2;" : "=f"(lo), "=f"(hi) : "l"(d));
}

// ---------------- init: zero small control arrays ----------------
__global__ void init_kernel() {
    int i = threadIdx.x;
    if (i < E) { g_counts[i] = 0; g_cursor[i] = 0; }
    if (i == 0) g_n_tiles = 0;
}

// ---------------- router GEMM: logits[T,32] = x @ gate_w^T + gate_b ----------------
__global__ __launch_bounds__(256) void router_gemm(const float* __restrict__ x,
                                                   const float* __restrict__ gw,
                                                   const float* __restrict__ gb) {
    __shared__ __align__(16) float xs[32][36];
    __shared__ __align__(16) float ws[32][36];
    int tid = threadIdx.x;
    int tx = tid & 7;          // expert group: 4 experts each
    int ty = tid >> 3;         // token 0..31
    int tbase = blockIdx.x * 32;
    int lrow = tid >> 3;       // 0..31 (load row)
    int lk4  = (tid & 7) * 4;  // 0..28

    float acc[4] = {0.f, 0.f, 0.f, 0.f};
    const float* xp = x  + (size_t)(tbase + lrow) * H + lk4;
    const float* wp = gw + (size_t)lrow * H + lk4;

    for (int kb = 0; kb < H; kb += 32) {
        float4 xv = *(const float4*)(xp + kb);
        float4 wv = *(const float4*)(wp + kb);
        *(float4*)&xs[lrow][lk4] = xv;
        ws[lk4 + 0][lrow] = wv.x;
        ws[lk4 + 1][lrow] = wv.y;
        ws[lk4 + 2][lrow] = wv.z;
        ws[lk4 + 3][lrow] = wv.w;
        __syncthreads();
#pragma unroll
        for (int k = 0; k < 32; ++k) {
            float xv1 = xs[ty][k];
            float4 w4 = *(const float4*)&ws[k][tx * 4];
            acc[0] = fmaf(xv1, w4.x, acc[0]);
            acc[1] = fmaf(xv1, w4.y, acc[1]);
            acc[2] = fmaf(xv1, w4.z, acc[2]);
            acc[3] = fmaf(xv1, w4.w, acc[3]);
        }
        __syncthreads();
    }
    int t = tbase + ty;
#pragma unroll
    for (int j = 0; j < 4; ++j)
        g_logits[t * E + tx * 4 + j] = acc[j] + gb[tx * 4 + j];
}

// ---------------- softmax + top-2 per token; count tokens per expert ----------------
__global__ void topk_kernel(int T) {
    int warp = (blockIdx.x * blockDim.x + threadIdx.x) >> 5;
    int lane = threadIdx.x & 31;
    if (warp >= T) return;
    float l = g_logits[warp * E + lane];

    float m = l;
#pragma unroll
    for (int o = 16; o; o >>= 1) m = fmaxf(m, __shfl_xor_sync(0xffffffffu, m, o));
    float p = __expf(l - m);
    float s = p;
#pragma unroll
    for (int o = 16; o; o >>= 1) s += __shfl_xor_sync(0xffffffffu, s, o);
    float prob = p / s;

    // top-1 (tie -> lower index, matching lax.top_k)
    float v = prob; int idx = lane;
#pragma unroll
    for (int o = 16; o; o >>= 1) {
        float vo = __shfl_xor_sync(0xffffffffu, v, o);
        int   io = __shfl_xor_sync(0xffffffffu, idx, o);
        if (vo > v || (vo == v && io < idx)) { v = vo; idx = io; }
    }
    int e0 = idx; float g0 = v;

    float v2 = (lane == e0) ? -1.0f : prob; int idx2 = lane;
#pragma unroll
    for (int o = 16; o; o >>= 1) {
        float vo = __shfl_xor_sync(0xffffffffu, v2, o);
        int   io = __shfl_xor_sync(0xffffffffu, idx2, o);
        if (vo > v2 || (vo == v2 && io < idx2)) { v2 = vo; idx2 = io; }
    }
    int e1 = idx2; float g1 = v2;

    if (lane == 0) {
        g_tok_e[warp * 2 + 0] = e0; g_tok_g[warp * 2 + 0] = g0;
        g_tok_e[warp * 2 + 1] = e1; g_tok_g[warp * 2 + 1] = g1;
        atomicAdd(&g_counts[e0], 1);
        atomicAdd(&g_counts[e1], 1);
    }
}

// ---------------- scan: expert offsets + tile list ----------------
__global__ void scan_kernel() {
    if (threadIdx.x != 0) return;
    int off = 0, nt = 0;
    for (int e = 0; e < E; ++e) {
        g_offsets[e] = off;
        int c = g_counts[e];
        for (int rb = 0; rb < c; rb += TM) {
            g_tile_expert[nt]   = e;
            g_tile_rowbase[nt]  = rb;
            g_tile_pairbase[nt] = off + rb;
            nt++;
        }
        off += c;
    }
    g_n_tiles = nt;
}

// ---------------- scatter tokens into per-expert contiguous pair lists ----------------
__global__ void scatter_kernel(int T) {
    int t = blockIdx.x * blockDim.x + threadIdx.x;
    if (t >= T) return;
#pragma unroll
    for (int j = 0; j < 2; ++j) {
        int e = g_tok_e[t * 2 + j];
        int pos = g_offsets[e] + atomicAdd(&g_cursor[e], 1);
        g_pair_tok[pos]  = t;
        g_pair_gate[pos] = g_tok_g[t * 2 + j];
    }
}

// ---------------- fc1: gathered GEMM [rows,2I] = X[tok] @ W1_e^T, fused swiglu -> g_h ----------------
__global__ __launch_bounds__(256) void fc1_kernel(const float* __restrict__ x,
                                                  const float* __restrict__ w1,
                                                  const float* __restrict__ b1) {
    int tile = blockIdx.x;
    if (tile >= g_n_tiles) return;
    int e         = g_tile_expert[tile];
    int rowbase   = g_tile_rowbase[tile];
    int pair_base = g_tile_pairbase[tile];
    int rows = g_counts[e] - rowbase; if (rows > TM) rows = TM;
    int nbase = blockIdx.y * TN;

    __shared__ __align__(16) float a_s[TK][TM + 4];
    __shared__ __align__(16) float b_s[TK][TN + 2];

    int tid = threadIdx.x;
    int tx = tid & 15, ty = tid >> 4;
    int lrow = tid >> 2, lk4 = (tid & 3) << 2;

    int arow = (lrow < rows) ? lrow : 0;
    int tok  = g_pair_tok[pair_base + arow];
    const float* aptr = x  + (size_t)tok * H + lk4;
    const float* bptr = w1 + ((size_t)e * I2 + (nbase + lrow)) * H + lk4;

    unsigned long long acc[4][2];
#pragma unroll
    for (int i = 0; i < 4; ++i) { acc[i][0] = 0ull; acc[i][1] = 0ull; }

    float4 areg = *(const float4*)aptr;
    float4 breg = *(const float4*)bptr;

    const int NK = H / TK;
    for (int kc = 0; kc < NK; ++kc) {
        a_s[lk4 + 0][lrow] = areg.x; a_s[lk4 + 1][lrow] = areg.y;
        a_s[lk4 + 2][lrow] = areg.z; a_s[lk4 + 3][lrow] = areg.w;
        b_s[lk4 + 0][lrow] = breg.x; b_s[lk4 + 1][lrow] = breg.y;
        b_s[lk4 + 2][lrow] = breg.z; b_s[lk4 + 3][lrow] = breg.w;
        __syncthreads();
        if (kc + 1 < NK) {
            areg = *(const float4*)(aptr + (kc + 1) * TK);
            breg = *(const float4*)(bptr + (kc + 1) * TK);
        }
#pragma unroll
        for (int k = 0; k < TK; ++k) {
            float4 av = *(const float4*)&a_s[k][ty * 4];
            const unsigned long long* brow = (const unsigned long long*)&b_s[k][0];
            unsigned long long bv0 = brow[tx * 2], bv1 = brow[tx * 2 + 1];
            unsigned long long a0 = packdup(av.x), a1 = packdup(av.y);
            unsigned long long a2 = packdup(av.z), a3 = packdup(av.w);
            FMA2(acc[0][0], a0, bv0); FMA2(acc[0][1], a0, bv1);
            FMA2(acc[1][0], a1, bv0); FMA2(acc[1][1], a1, bv1);
            FMA2(acc[2][0], a2, bv0); FMA2(acc[2][1], a2, bv1);
            FMA2(acc[3][0], a3, bv0); FMA2(acc[3][1], a3, bv1);
        }
        __syncthreads();
    }

    const float* b1e = b1 + e * I2;
#pragma unroll
    for (int i = 0; i < 4; ++i) {
        int lm = ty * 4 + i;
        if (lm >= rows) continue;
        int pair = pair_base + lm;
#pragma unroll
        for (int jj = 0; jj < 2; ++jj) {
            float zg, zl;
            unpack2(acc[i][jj], zg, zl);
            int ncol = nbase + tx * 4 + jj * 2;        // even column -> glu path
            zg += b1e[ncol];
            zl += b1e[ncol + 1];
            zg = fminf(zg, 7.0f);
            zl = fminf(fmaxf(zl, -7.0f), 7.0f);
            float hv = zg * (1.0f / (1.0f + __expf(-1.702f * zg))) * (zl + 1.0f);
            g_h[pair * I1 + (ncol >> 1)] = hv;
        }
    }
}

// ---------------- fc2: [rows,H] = h @ W2_e^T (+b2), scaled by gate, atomic-scatter to out ----------------
__global__ __launch_bounds__(256) void fc2_kernel(const float* __restrict__ w2,
                                                  const float* __restrict__ b2,
                                                  float* __restrict__ out,
                                                  int total_pairs) {
    int tile = blockIdx.x;
    if (tile >= g_n_tiles) return;
    int e         = g_tile_expert[tile];
    int rowbase   = g_tile_rowbase[tile];
    int pair_base = g_tile_pairbase[tile];
    int rows = g_counts[e] - rowbase; if (rows > TM) rows = TM;
    int nbase = blockIdx.y * TN;

    __shared__ __align__(16) float a_s[TK][TM + 4];
    __shared__ __align__(16) float b_s[TK][TN + 2];

    int tid = threadIdx.x;
    int tx = tid & 15, ty = tid >> 4;
    int lrow = tid >> 2, lk4 = (tid & 3) << 2;

    int prow = pair_base + lrow;
    if (prow >= total_pairs) prow = total_pairs - 1;
    const float* aptr = g_h + (size_t)prow * I1 + lk4;
    const float* bptr = w2  + ((size_t)e * H + (nbase + lrow)) * I1 + lk4;

    unsigned long long acc[4][2];
#pragma unroll
    for (int i = 0; i < 4; ++i) { acc[i][0] = 0ull; acc[i][1] = 0ull; }

    float4 areg = *(const float4*)aptr;
    float4 breg = *(const float4*)bptr;

    const int NK = I1 / TK;
    for (int kc = 0; kc < NK; ++kc) {
        a_s[lk4 + 0][lrow] = areg.x; a_s[lk4 + 1][lrow] = areg.y;
        a_s[lk4 + 2][lrow] = areg.z; a_s[lk4 + 3][lrow] = areg.w;
        b_s[lk4 + 0][lrow] = breg.x; b_s[lk4 + 1][lrow] = breg.y;
        b_s[lk4 + 2][lrow] = breg.z; b_s[lk4 + 3][lrow] = breg.w;
        __syncthreads();
        if (kc + 1 < NK) {
            areg = *(const float4*)(aptr + (kc + 1) * TK);
            breg = *(const float4*)(bptr + (kc + 1) * TK);
        }
#pragma unroll
        for (int k = 0; k < TK; ++k) {
            float4 av = *(const float4*)&a_s[k][ty * 4];
            const unsigned long long* brow = (const unsigned long long*)&b_s[k][0];
            unsigned long long bv0 = brow[tx * 2], bv1 = brow[tx * 2 + 1];
            unsigned long long a0 = packdup(av.x), a1 = packdup(av.y);
            unsigned long long a2 = packdup(av.z), a3 = packdup(av.w);
            FMA2(acc[0][0], a0, bv0); FMA2(acc[0][1], a0, bv1);
            FMA2(acc[1][0], a1, bv0); FMA2(acc[1][1], a1, bv1);
            FMA2(acc[2][0], a2, bv0); FMA2(acc[2][1], a2, bv1);
            FMA2(acc[3][0], a3, bv0); FMA2(acc[3][1], a3, bv1);
        }
        __syncthreads();
    }

    const float* b2e = b2 + e * H;
#pragma unroll
    for (int i = 0; i < 4; ++i) {
        int lm = ty * 4 + i;
        if (lm >= rows) continue;
        int pair = pair_base + lm;
        int tok  = g_pair_tok[pair];
        float gate = g_pair_gate[pair];
        float* orow = out + (size_t)tok * H;
#pragma unroll
        for (int jj = 0; jj < 2; ++jj) {
            float y0, y1;
            unpack2(acc[i][jj], y0, y1);
            int ncol = nbase + tx * 4 + jj * 2;
            atomicAdd(orow + ncol,     gate * (y0 + b2e[ncol]));
            atomicAdd(orow + ncol + 1, gate * (y1 + b2e[ncol + 1]));
        }
    }
}

// ---------------- launch ----------------
extern "C" void kernel_launch(void* const* d_in, const int* in_sizes, int n_in,
                              void* d_out, int out_size) {
    const float* x  = (const float*)d_in[0];
    const float* gw = (const float*)d_in[1];
    const float* gb = (const float*)d_in[2];
    const float* w1 = (const float*)d_in[3];
    const float* b1 = (const float*)d_in[4];
    const float* w2 = (const float*)d_in[5];
    const float* b2 = (const float*)d_in[6];
    float* out = (float*)d_out;
    int T = in_sizes[0] / H;   // 8192

    cudaMemsetAsync(d_out, 0, (size_t)out_size * sizeof(float));
    init_kernel<<<1, 64>>>();
    router_gemm<<<T / 32, 256>>>(x, gw, gb);
    topk_kernel<<<(T + 7) / 8, 256>>>(T);
    scan_kernel<<<1, 32>>>();
    scatter_kernel<<<(T + 255) / 256, 256>>>(T);

    dim3 g1(MAXTILES, I2 / TN);   // (320, 32)
    fc1_kernel<<<g1, 256>>>(x, w1, b1);
    dim3 g2(MAXTILES, H / TN);    // (320, 32)
    fc2_kernel<<<g2, 256>>>(w2, b2, out, 2 * T);
}

// round 9
// speedup vs baseline: 3.4837x; 3.4782x over previous
#include <cuda_runtime.h>
#include <cuda_bf16.h>
#include <cstdint>

#define H   2048
#define I1  1024
#define I2  2048
#define E   32
#define MAXT 8192
#define MAXPAIR (2*MAXT)
#define MAXPAIRP (MAXPAIR + 128)
#define MAXTILES 160
#define TMM 128          // CTA M tile
#define TNN 128          // CTA N tile
#define KC  64           // K chunk (bf16 elems) = 128B SW128 row
#define TILE_B 16384     // one 128x64 bf16 tile
#define STAGE_BYTES (4*TILE_B)      /* Ahi Alo Bhi Blo = 64KB */
#define SMEM_DYN (2*STAGE_BYTES)    /* 128KB double buffer */

// ---------------- device scratch ----------------
__device__ uint4 g_xhi4[(size_t)MAXPAIRP*(H/8)];
__device__ uint4 g_xlo4[(size_t)MAXPAIRP*(H/8)];
__device__ uint4 g_w1hi4[(size_t)E*I2*(H/8)];
__device__ uint4 g_w1lo4[(size_t)E*I2*(H/8)];
__device__ uint4 g_w2hi4[(size_t)E*H*(I1/8)];
__device__ uint4 g_w2lo4[(size_t)E*H*(I1/8)];
__device__ uint4 g_hhi4[(size_t)MAXPAIRP*(I1/8)];
__device__ uint4 g_hlo4[(size_t)MAXPAIRP*(I1/8)];

__device__ float g_logits[MAXT * E];
__device__ int   g_counts[E];
__device__ int   g_cursor[E];
__device__ int   g_offsets[E];
__device__ int   g_tok_e[MAXT * 2];
__device__ float g_tok_g[MAXT * 2];
__device__ int   g_pair_tok[MAXPAIR];
__device__ float g_pair_gate[MAXPAIR];
__device__ int   g_tile_expert[MAXTILES];
__device__ int   g_tile_rowbase[MAXTILES];
__device__ int   g_tile_pairbase[MAXTILES];
__device__ int   g_n_tiles;

// ---------------- PTX helpers (all plain-sm_103-legal) ----------------
__device__ __forceinline__ uint32_t smem_u32(const void* p) {
    uint32_t a;
    asm("{ .reg .u64 t; cvta.to.shared.u64 t, %1; cvt.u32.u64 %0, t; }" : "=r"(a) : "l"(p));
    return a;
}
__device__ __forceinline__ void cp16(uint32_t s, const void* g) {
    asm volatile("cp.async.cg.shared.global [%0], [%1], 16;" :: "r"(s), "l"(g));
}
#define CP_COMMIT() asm volatile("cp.async.commit_group;" ::: "memory")
#define CP_WAIT(n)  asm volatile("cp.async.wait_group %0;" :: "n"(n) : "memory")

__device__ __forceinline__ void ldm_x4(uint32_t r[4], uint32_t addr) {
    asm volatile("ldmatrix.sync.aligned.m8n8.x4.shared.b16 {%0,%1,%2,%3}, [%4];"
        : "=r"(r[0]), "=r"(r[1]), "=r"(r[2]), "=r"(r[3]) : "r"(addr));
}
__device__ __forceinline__ void mma16816(float c[4], const uint32_t a[4],
                                         uint32_t b0, uint32_t b1) {
    asm volatile("mma.sync.aligned.m16n8k16.row.col.f32.bf16.bf16.f32 "
        "{%0,%1,%2,%3}, {%4,%5,%6,%7}, {%8,%9}, {%0,%1,%2,%3};"
        : "+f"(c[0]), "+f"(c[1]), "+f"(c[2]), "+f"(c[3])
        : "r"(a[0]), "r"(a[1]), "r"(a[2]), "r"(a[3]), "r"(b0), "r"(b1));
}
__device__ __forceinline__ uint32_t swz(uint32_t x) { return x ^ ((x >> 3) & 0x70); }

__device__ __forceinline__ void split8(const float4& a, const float4& b, uint4& hi, uint4& lo) {
    float f[8] = {a.x, a.y, a.z, a.w, b.x, b.y, b.z, b.w};
    unsigned v[8], w[8];
#pragma unroll
    for (int j = 0; j < 8; j++) {
        __nv_bfloat16 x = __float2bfloat16(f[j]);
        v[j] = (unsigned)__bfloat16_as_ushort(x);
        w[j] = (unsigned)__bfloat16_as_ushort(__float2bfloat16(f[j] - __bfloat162float(x)));
    }
    hi = make_uint4(v[0]|(v[1]<<16), v[2]|(v[3]<<16), v[4]|(v[5]<<16), v[6]|(v[7]<<16));
    lo = make_uint4(w[0]|(w[1]<<16), w[2]|(w[3]<<16), w[4]|(w[5]<<16), w[6]|(w[7]<<16));
}

// ---------------- routing kernels ----------------
__global__ void init_kernel() {
    int i = threadIdx.x;
    if (i < E) { g_counts[i] = 0; g_cursor[i] = 0; }
    if (i == 0) g_n_tiles = 0;
}

__global__ __launch_bounds__(256) void router_gemm(const float* __restrict__ x,
                                                   const float* __restrict__ gw,
                                                   const float* __restrict__ gb) {
    __shared__ __align__(16) float xs[32][36];
    __shared__ __align__(16) float ws[32][36];
    int tid = threadIdx.x;
    int tx = tid & 7, ty = tid >> 3;
    int tbase = blockIdx.x * 32;
    int lrow = tid >> 3, lk4 = (tid & 7) * 4;
    float acc[4] = {0.f, 0.f, 0.f, 0.f};
    const float* xp = x  + (size_t)(tbase + lrow) * H + lk4;
    const float* wp = gw + (size_t)lrow * H + lk4;
    for (int kb = 0; kb < H; kb += 32) {
        float4 xv = *(const float4*)(xp + kb);
        float4 wv = *(const float4*)(wp + kb);
        *(float4*)&xs[lrow][lk4] = xv;
        ws[lk4+0][lrow] = wv.x; ws[lk4+1][lrow] = wv.y;
        ws[lk4+2][lrow] = wv.z; ws[lk4+3][lrow] = wv.w;
        __syncthreads();
#pragma unroll
        for (int k = 0; k < 32; ++k) {
            float xv1 = xs[ty][k];
            float4 w4 = *(const float4*)&ws[k][tx*4];
            acc[0] = fmaf(xv1, w4.x, acc[0]); acc[1] = fmaf(xv1, w4.y, acc[1]);
            acc[2] = fmaf(xv1, w4.z, acc[2]); acc[3] = fmaf(xv1, w4.w, acc[3]);
        }
        __syncthreads();
    }
    int t = tbase + ty;
#pragma unroll
    for (int j = 0; j < 4; ++j) g_logits[t*E + tx*4 + j] = acc[j] + gb[tx*4 + j];
}

__global__ void topk_kernel(int T) {
    int warp = (blockIdx.x * blockDim.x + threadIdx.x) >> 5;
    int lane = threadIdx.x & 31;
    if (warp >= T) return;
    float l = g_logits[warp * E + lane];
    float m = l;
#pragma unroll
    for (int o = 16; o; o >>= 1) m = fmaxf(m, __shfl_xor_sync(0xffffffffu, m, o));
    float p = __expf(l - m);
    float s = p;
#pragma unroll
    for (int o = 16; o; o >>= 1) s += __shfl_xor_sync(0xffffffffu, s, o);
    float prob = p / s;
    float v = prob; int idx = lane;
#pragma unroll
    for (int o = 16; o; o >>= 1) {
        float vo = __shfl_xor_sync(0xffffffffu, v, o);
        int   io = __shfl_xor_sync(0xffffffffu, idx, o);
        if (vo > v || (vo == v && io < idx)) { v = vo; idx = io; }
    }
    int e0 = idx; float g0 = v;
    float v2 = (lane == e0) ? -1.0f : prob; int idx2 = lane;
#pragma unroll
    for (int o = 16; o; o >>= 1) {
        float vo = __shfl_xor_sync(0xffffffffu, v2, o);
        int   io = __shfl_xor_sync(0xffffffffu, idx2, o);
        if (vo > v2 || (vo == v2 && io < idx2)) { v2 = vo; idx2 = io; }
    }
    if (lane == 0) {
        g_tok_e[warp*2+0] = e0;   g_tok_g[warp*2+0] = g0;
        g_tok_e[warp*2+1] = idx2; g_tok_g[warp*2+1] = v2;
        atomicAdd(&g_counts[e0], 1);
        atomicAdd(&g_counts[idx2], 1);
    }
}

__global__ void scan_kernel() {
    if (threadIdx.x != 0) return;
    int off = 0, nt = 0;
    for (int e = 0; e < E; ++e) {
        g_offsets[e] = off;
        int c = g_counts[e];
        for (int rb = 0; rb < c; rb += TMM) {
            g_tile_expert[nt] = e; g_tile_rowbase[nt] = rb; g_tile_pairbase[nt] = off + rb;
            nt++;
        }
        off += c;
    }
    g_n_tiles = nt;
}

__global__ void scatter_kernel(int T) {
    int t = blockIdx.x * blockDim.x + threadIdx.x;
    if (t >= T) return;
#pragma unroll
    for (int j = 0; j < 2; ++j) {
        int e = g_tok_e[t*2+j];
        int pos = g_offsets[e] + atomicAdd(&g_cursor[e], 1);
        g_pair_tok[pos]  = t;
        g_pair_gate[pos] = g_tok_g[t*2+j];
    }
}

// ---------------- split / gather ----------------
__global__ __launch_bounds__(256) void split_w1(const float4* __restrict__ src) {
    size_t i = (size_t)blockIdx.x * 256 + threadIdx.x;
    if (i >= (size_t)E*I2*(H/8)) return;
    uint4 hi, lo; split8(src[i*2], src[i*2+1], hi, lo);
    g_w1hi4[i] = hi; g_w1lo4[i] = lo;
}
__global__ __launch_bounds__(256) void split_w2(const float4* __restrict__ src) {
    size_t i = (size_t)blockIdx.x * 256 + threadIdx.x;
    if (i >= (size_t)E*H*(I1/8)) return;
    uint4 hi, lo; split8(src[i*2], src[i*2+1], hi, lo);
    g_w2hi4[i] = hi; g_w2lo4[i] = lo;
}
__global__ __launch_bounds__(256) void gather_x(const float* __restrict__ x) {
    int p = blockIdx.x, tid = threadIdx.x;
    int tok = g_pair_tok[p];
    const float4* src = (const float4*)(x + (size_t)tok * H);
    uint4 hi, lo; split8(src[tid*2], src[tid*2+1], hi, lo);
    g_xhi4[(size_t)p*(H/8) + tid] = hi;
    g_xlo4[(size_t)p*(H/8) + tid] = lo;
}

// ---------------- grouped GEMM building blocks ----------------
// stage: fill one 64KB stage (Ahi|Alo|Bhi|Blo, each 128 rows x 128B, SW128)
__device__ __forceinline__ void stage4(uint32_t dst,
    const uint4* __restrict__ ahi, const uint4* __restrict__ alo, int ars,
    const uint4* __restrict__ bhi, const uint4* __restrict__ blo, int brs,
    int k8, int tid)
{
    int r0 = tid >> 3, c = tid & 7;
#pragma unroll
    for (int p = 0; p < 4; p++) {
        int r = r0 + p * 32;
        uint32_t d = swz((uint32_t)(r * 128 + c * 16));
        size_t aoff = (size_t)r * ars + (k8 + c);
        size_t boff = (size_t)r * brs + (k8 + c);
        cp16(dst +            d, ahi + aoff);
        cp16(dst +   TILE_B + d, alo + aoff);
        cp16(dst + 2*TILE_B + d, bhi + boff);
        cp16(dst + 3*TILE_B + d, blo + boff);
    }
}

// compute one KC=64 stage: 4 k16 steps, 3-term split MMA
__device__ __forceinline__ void compute_stage(uint32_t sbuf, float acc[4][4][4],
                                              int arow, int brow, int kA, int kB,
                                              uint32_t kxor)
{
    uint32_t ab = sbuf, bb = sbuf + 2*TILE_B;
#pragma unroll
    for (int ks = 0; ks < 4; ks++) {
        uint32_t Ah[4][4], Al[4][4], Bh[2][4], Bl[2][4];
#pragma unroll
        for (int mt = 0; mt < 4; mt++) {
            int row = arow + mt * 16;
            uint32_t off = (uint32_t)(row * 128) + (((uint32_t)(ks*32 + kA)) ^ kxor);
            ldm_x4(Ah[mt], ab + off);
            ldm_x4(Al[mt], ab + TILE_B + off);
        }
#pragma unroll
        for (int np = 0; np < 2; np++) {
            int row = brow + np * 16;
            uint32_t off = (uint32_t)(row * 128) + (((uint32_t)(ks*32 + kB)) ^ kxor);
            ldm_x4(Bh[np], bb + off);
            ldm_x4(Bl[np], bb + TILE_B + off);
        }
#pragma unroll
        for (int mt = 0; mt < 4; mt++) {
#pragma unroll
            for (int nt = 0; nt < 4; nt++) {
                const uint32_t* bh = &Bh[nt >> 1][(nt & 1) * 2];
                const uint32_t* bl = &Bl[nt >> 1][(nt & 1) * 2];
                mma16816(acc[mt][nt], Ah[mt], bh[0], bh[1]);   // hi*hi
                mma16816(acc[mt][nt], Ah[mt], bl[0], bl[1]);   // hi*lo
                mma16816(acc[mt][nt], Al[mt], bh[0], bh[1]);   // lo*hi
            }
        }
    }
}

__device__ __forceinline__ void gemm_mainloop(uint32_t tb, float acc[4][4][4],
    const uint4* ahi, const uint4* alo, int ars,
    const uint4* bhi, const uint4* blo, int brs,
    int nkc, int tid)
{
    int lane = tid & 31, wid = tid >> 5;
    int warp_m = wid >> 2, warp_n = wid & 3;
    int g = lane >> 3, rowin = lane & 7;
    // A: row += (g&1)*8, koff = (g>>1)*16 ; B: row += (g>>1)*8, koff = (g&1)*16
    int arow = warp_m * 64 + (g & 1) * 8 + rowin;
    int brow = warp_n * 32 + (g >> 1) * 8 + rowin;
    int kA = (g >> 1) * 16, kB = (g & 1) * 16;
    uint32_t kxor = (uint32_t)rowin << 4;

    stage4(tb, ahi, alo, ars, bhi, blo, brs, 0, tid);
    CP_COMMIT();
    for (int kc = 0; kc < nkc; kc++) {
        int buf = kc & 1;
        if (kc + 1 < nkc) {
            stage4(tb + (buf ^ 1) * STAGE_BYTES, ahi, alo, ars, bhi, blo, brs,
                   (kc + 1) * (KC / 8), tid);
            CP_COMMIT();
            CP_WAIT(1);
        } else {
            CP_WAIT(0);
        }
        __syncthreads();
        compute_stage(tb + buf * STAGE_BYTES, acc, arow, brow, kA, kB, kxor);
        __syncthreads();
    }
}

// ---------------- fc1: X @ W1^T (+b1) -> swiglu -> split-bf16 h ----------------
__global__ void __launch_bounds__(256, 1)
fc1_mma(const float* __restrict__ b1) {
    int tile = blockIdx.y;
    if (tile >= g_n_tiles) return;
    int e = g_tile_expert[tile];
    int pair_base = g_tile_pairbase[tile];
    int rows = g_counts[e] - g_tile_rowbase[tile]; if (rows > TMM) rows = TMM;
    int nbase = blockIdx.x * TNN;

    extern __shared__ __align__(1024) char smem[];
    uint32_t tb = smem_u32(smem);
    int tid = threadIdx.x;

    float acc[4][4][4];
#pragma unroll
    for (int a = 0; a < 4; a++)
#pragma unroll
        for (int b = 0; b < 4; b++)
#pragma unroll
            for (int c = 0; c < 4; c++) acc[a][b][c] = 0.f;

    gemm_mainloop(tb, acc,
        g_xhi4 + (size_t)pair_base*(H/8), g_xlo4 + (size_t)pair_base*(H/8), H/8,
        g_w1hi4 + ((size_t)e*I2 + nbase)*(H/8), g_w1lo4 + ((size_t)e*I2 + nbase)*(H/8), H/8,
        H/KC, tid);

    int lane = tid & 31, wid = tid >> 5;
    int warp_m = wid >> 2, warp_n = wid & 3;
    const float* b1e = b1 + (size_t)e*I2 + nbase;
    __nv_bfloat16* hhB = (__nv_bfloat16*)g_hhi4;
    __nv_bfloat16* hlB = (__nv_bfloat16*)g_hlo4;
#pragma unroll
    for (int mt = 0; mt < 4; mt++) {
#pragma unroll
        for (int hf = 0; hf < 2; hf++) {
            int row = warp_m*64 + mt*16 + (lane >> 2) + hf*8;
            if (row >= rows) continue;
            int pair = pair_base + row;
            size_t hbase = (size_t)pair * I1 + (nbase >> 1);
#pragma unroll
            for (int nt = 0; nt < 4; nt++) {
                int n = warp_n*32 + nt*8 + (lane & 3)*2;
                float zg = acc[mt][nt][hf*2]     + b1e[n];
                float zl = acc[mt][nt][hf*2 + 1] + b1e[n + 1];
                zg = fminf(zg, 7.0f);
                zl = fminf(fmaxf(zl, -7.0f), 7.0f);
                float hv = zg * (1.0f/(1.0f + __expf(-1.702f*zg))) * (zl + 1.0f);
                __nv_bfloat16 hb = __float2bfloat16(hv);
                hhB[hbase + (n >> 1)] = hb;
                hlB[hbase + (n >> 1)] = __float2bfloat16(hv - __bfloat162float(hb));
            }
        }
    }
}

// ---------------- fc2: h @ W2^T (+b2), gate-scaled atomic scatter ----------------
__global__ void __launch_bounds__(256, 1)
fc2_mma(const float* __restrict__ b2, float* __restrict__ out) {
    int tile = blockIdx.y;
    if (tile >= g_n_tiles) return;
    int e = g_tile_expert[tile];
    int pair_base = g_tile_pairbase[tile];
    int rows = g_counts[e] - g_tile_rowbase[tile]; if (rows > TMM) rows = TMM;
    int nbase = blockIdx.x * TNN;

    extern __shared__ __align__(1024) char smem[];
    uint32_t tb = smem_u32(smem);
    int tid = threadIdx.x;

    float acc[4][4][4];
#pragma unroll
    for (int a = 0; a < 4; a++)
#pragma unroll
        for (int b = 0; b < 4; b++)
#pragma unroll
            for (int c = 0; c < 4; c++) acc[a][b][c] = 0.f;

    gemm_mainloop(tb, acc,
        g_hhi4 + (size_t)pair_base*(I1/8), g_hlo4 + (size_t)pair_base*(I1/8), I1/8,
        g_w2hi4 + ((size_t)e*H + nbase)*(I1/8), g_w2lo4 + ((size_t)e*H + nbase)*(I1/8), I1/8,
        I1/KC, tid);

    int lane = tid & 31, wid = tid >> 5;
    int warp_m = wid >> 2, warp_n = wid & 3;
    const float* b2e = b2 + (size_t)e*H + nbase;
#pragma unroll
    for (int mt = 0; mt < 4; mt++) {
#pragma unroll
        for (int hf = 0; hf < 2; hf++) {
            int row = warp_m*64 + mt*16 + (lane >> 2) + hf*8;
            if (row >= rows) continue;
            int pair = pair_base + row;
            int tok = g_pair_tok[pair];
            float gate = g_pair_gate[pair];
            float* orow = out + (size_t)tok*H + nbase;
#pragma unroll
            for (int nt = 0; nt < 4; nt++) {
                int n = warp_n*32 + nt*8 + (lane & 3)*2;
                float y0 = acc[mt][nt][hf*2]     + b2e[n];
                float y1 = acc[mt][nt][hf*2 + 1] + b2e[n + 1];
                atomicAdd(orow + n,     gate * y0);
                atomicAdd(orow + n + 1, gate * y1);
            }
        }
    }
}

// ---------------- launch ----------------
extern "C" void kernel_launch(void* const* d_in, const int* in_sizes, int n_in,
                              void* d_out, int out_size) {
    const float* x  = (const float*)d_in[0];
    const float* gw = (const float*)d_in[1];
    const float* gb = (const float*)d_in[2];
    const float* w1 = (const float*)d_in[3];
    const float* b1 = (const float*)d_in[4];
    const float* w2 = (const float*)d_in[5];
    const float* b2 = (const float*)d_in[6];
    float* out = (float*)d_out;
    int T = in_sizes[0] / H;   // 8192

    cudaFuncSetAttribute(fc1_mma, cudaFuncAttributeMaxDynamicSharedMemorySize, SMEM_DYN);
    cudaFuncSetAttribute(fc2_mma, cudaFuncAttributeMaxDynamicSharedMemorySize, SMEM_DYN);

    cudaMemsetAsync(d_out, 0, (size_t)out_size * sizeof(float));
    init_kernel<<<1, 64>>>();
    router_gemm<<<T / 32, 256>>>(x, gw, gb);
    topk_kernel<<<(T + 7) / 8, 256>>>(T);
    scan_kernel<<<1, 32>>>();
    scatter_kernel<<<(T + 255) / 256, 256>>>(T);

    split_w1<<<(int)(((size_t)E*I2*(H/8) + 255) / 256), 256>>>((const float4*)w1);
    split_w2<<<(int)(((size_t)E*H*(I1/8) + 255) / 256), 256>>>((const float4*)w2);
    gather_x<<<2 * T, 256>>>(x);

    fc1_mma<<<dim3(I2 / TNN, MAXTILES), 256, SMEM_DYN>>>(b1);
    fc2_mma<<<dim3(H / TNN, MAXTILES), 256, SMEM_DYN>>>(b2, out);
}